// round 8
// baseline (speedup 1.0000x reference)
#include <cuda_runtime.h>
#include <cuda_fp16.h>
#include <cstdint>

// ---------------------------------------------------------------------------
// AttentionPool: B=8, N=4096, DIM=1536, H=24, hd=64, R=8
// Reformulated (8x FLOP cut) + fp16 MMA (m16n8k16) for both big GEMMs:
//   x_h  = fp16(x)        [b][n][c]   (for logits B)
//   x_t  = fp16(x^T)      [b][c][n]   (for y B; n-contiguous k-pairs)
//   q    = (x[:, :8] @ Wq^T) * SCALE
//   qkh[b,g,c]  = fp16( sum_d q * Wk )            g = h*8+r
//   logits[b,g,n] = sum_c qkh * x_h    (fp16 MMA, fp32 accum)
//   p_h  = fp16( masked softmax(logits) )
//   y[b,g,c] = sum_n p_h * x_t         (fp16 MMA, fp32 accum)
//   xcls = per-head Wv projection of y;  out = xcls @ Wp^T + bp
// ---------------------------------------------------------------------------

#define DIMC   1536
#define NTOK   4096
#define NB     8
#define NH     24
#define HD     64
#define RR     8
#define NG     192
#define SCALE  0.125f
#define MASKW  4088

// ------------------------- scratch (static device memory) ------------------
__device__ float    g_x8[64 * DIMC];
__device__ float    g_q[64 * DIMC];
__device__ float    g_part[6 * 64 * DIMC];
__device__ float    g_p[NB * NG * NTOK];             // fp32 logits
__device__ float    g_y[NB * NG * DIMC];
__device__ float    g_xcls[64 * DIMC];
__device__ int      g_maskmode;
// fp16 (packed as uint32 k-pairs)
__device__ uint32_t g_xh [NB * NTOK * (DIMC / 2)];   // [b][n][c/2]   100MB
__device__ uint32_t g_xt [NB * DIMC * (NTOK / 2)];   // [b][c][n/2]   100MB
__device__ uint32_t g_qkh[NB * NG   * (DIMC / 2)];   // [b][g][c/2]
__device__ uint32_t g_ph [NB * NG   * (NTOK / 2)];   // [b][g][n/2]

// ------------------------- helpers -----------------------------------------
__device__ __forceinline__ void mma_f16(float* c, const uint32_t* a, const uint32_t* b) {
    asm volatile(
        "mma.sync.aligned.m16n8k16.row.col.f32.f16.f16.f32 "
        "{%0,%1,%2,%3}, {%4,%5,%6,%7}, {%8,%9}, {%0,%1,%2,%3};"
        : "+f"(c[0]), "+f"(c[1]), "+f"(c[2]), "+f"(c[3])
        : "r"(a[0]), "r"(a[1]), "r"(a[2]), "r"(a[3]),
          "r"(b[0]), "r"(b[1]));
}

// ------------------------- mask dtype detection -----------------------------
__global__ void detect_mask_kernel(const unsigned int* __restrict__ m) {
    __shared__ int s_f, s_nb;
    if (threadIdx.x == 0) { s_f = 0; s_nb = 0; }
    __syncthreads();
    unsigned int w = m[threadIdx.x];
    if (w == 0x3F800000u) atomicOr(&s_f, 1);
    else if (w > 1u)      atomicOr(&s_nb, 1);
    __syncthreads();
    if (threadIdx.x == 0) g_maskmode = s_f ? 2 : (s_nb ? 1 : 0);
}

// ------------------------- x -> fp16 (n-major) + fp16 transpose (c-major) ---
// tile 64n x 64c per block; grid (c-tiles 24, n-tiles 64, b)
__global__ __launch_bounds__(256)
void conv_kernel(const float* __restrict__ x) {
    int b = blockIdx.z;
    int n0 = blockIdx.y * 64, c0 = blockIdx.x * 64;
    __shared__ __half s[64][66];                  // [c_local][n_local], pad 2
    const float* xb = x + (size_t)b * NTOK * DIMC;
    int tid = threadIdx.x;
#pragma unroll
    for (int i = 0; i < 8; i++) {
        int w = tid + 256 * i;                    // word index: 64n x 32cw
        int nl = w >> 5, cw = w & 31;
        float2 v = *(const float2*)&xb[(size_t)(n0 + nl) * DIMC + c0 + 2 * cw];
        __half2 h2 = __floats2half2_rn(v.x, v.y);
        g_xh[(size_t)(b * NTOK + n0 + nl) * (DIMC / 2) + (c0 >> 1) + cw] =
            *(uint32_t*)&h2;
        s[2 * cw][nl]     = __low2half(h2);
        s[2 * cw + 1][nl] = __high2half(h2);
    }
    __syncthreads();
#pragma unroll
    for (int i = 0; i < 8; i++) {
        int w = tid + 256 * i;                    // word index: 64c x 32nw
        int cl = w >> 5, nw = w & 31;
        uint32_t word = *(const uint32_t*)&s[cl][2 * nw];
        g_xt[(size_t)(b * DIMC + c0 + cl) * (NTOK / 2) + (n0 >> 1) + nw] = word;
    }
}

// ------------------------- gather first 8 tokens ----------------------------
__global__ void gather_x8_kernel(const float* __restrict__ x) {
    int row = blockIdx.x;
    int b = row >> 3, r = row & 7;
    const float* src = x + ((size_t)b * NTOK + r) * DIMC;
    float* dst = g_x8 + (size_t)row * DIMC;
    for (int c = threadIdx.x; c < DIMC; c += blockDim.x) dst[c] = src[c];
}

// ------------------------- small NT GEMM with split-K (fp32) ----------------
__global__ __launch_bounds__(256)
void small_nt_kernel(const float* __restrict__ A, const float* __restrict__ B,
                     float* __restrict__ Cpart) {
    int n0 = blockIdx.x * 64;
    int ks = blockIdx.y;
    int kbase = ks * 256;
    __shared__ float As[64 * 33];
    __shared__ float Bs[64 * 33];
    int tid = threadIdx.x;
    int tx = tid & 15, ty = tid >> 4;
    float acc[4][4];
#pragma unroll
    for (int i = 0; i < 4; i++)
#pragma unroll
        for (int j = 0; j < 4; j++) acc[i][j] = 0.f;

    for (int kt = 0; kt < 8; kt++) {
        int kb = kbase + kt * 32;
        __syncthreads();
#pragma unroll
        for (int j = 0; j < 2; j++) {
            int idx = tid + 256 * j;
            int m = idx >> 3, k4 = (idx & 7) * 4;
            float4 va = *(const float4*)&A[(size_t)m * DIMC + kb + k4];
            As[m * 33 + k4 + 0] = va.x; As[m * 33 + k4 + 1] = va.y;
            As[m * 33 + k4 + 2] = va.z; As[m * 33 + k4 + 3] = va.w;
            float4 vb = *(const float4*)&B[(size_t)(n0 + m) * DIMC + kb + k4];
            Bs[m * 33 + k4 + 0] = vb.x; Bs[m * 33 + k4 + 1] = vb.y;
            Bs[m * 33 + k4 + 2] = vb.z; Bs[m * 33 + k4 + 3] = vb.w;
        }
        __syncthreads();
#pragma unroll
        for (int k = 0; k < 32; k++) {
            float a[4], bb[4];
#pragma unroll
            for (int i = 0; i < 4; i++) a[i]  = As[(ty * 4 + i) * 33 + k];
#pragma unroll
            for (int j = 0; j < 4; j++) bb[j] = Bs[(tx * 4 + j) * 33 + k];
#pragma unroll
            for (int i = 0; i < 4; i++)
#pragma unroll
                for (int j = 0; j < 4; j++) acc[i][j] += a[i] * bb[j];
        }
    }
#pragma unroll
    for (int i = 0; i < 4; i++)
#pragma unroll
        for (int j = 0; j < 4; j++)
            Cpart[(size_t)ks * 64 * DIMC + (ty * 4 + i) * DIMC + n0 + tx * 4 + j] = acc[i][j];
}

__global__ void reduce_q_kernel() {
    int i = blockIdx.x * 256 + threadIdx.x;
    if (i < 64 * DIMC) {
        float s = 0.f;
#pragma unroll
        for (int ks = 0; ks < 6; ks++) s += g_part[(size_t)ks * 64 * DIMC + i];
        g_q[i] = s * SCALE;
    }
}

__global__ void reduce_out_kernel(const float* __restrict__ bp, float* __restrict__ out) {
    int i = blockIdx.x * 256 + threadIdx.x;
    if (i < 64 * DIMC) {
        float s = bp[i % DIMC];
#pragma unroll
        for (int ks = 0; ks < 6; ks++) s += g_part[(size_t)ks * 64 * DIMC + i];
        out[i] = s;
    }
}

// ------------------------- qk = q @ Wk per head (fp32 math, fp16 out) -------
__global__ __launch_bounds__(128)
void qk_kernel(const float* __restrict__ Wk) {
    int b = blockIdx.z, h = blockIdx.y;
    int c = blockIdx.x * 128 + threadIdx.x;
    __shared__ float qs[8][64];
    for (int idx = threadIdx.x; idx < 512; idx += 128) {
        int r = idx >> 6, d = idx & 63;
        qs[r][d] = g_q[(size_t)(b * 8 + r) * DIMC + h * HD + d];
    }
    __syncthreads();
    float acc[8];
#pragma unroll
    for (int r = 0; r < 8; r++) acc[r] = 0.f;
    for (int d = 0; d < 64; d++) {
        float w = Wk[(size_t)(h * HD + d) * DIMC + c];
#pragma unroll
        for (int r = 0; r < 8; r++) acc[r] += qs[r][d] * w;
    }
    __half* dst = (__half*)g_qkh;
#pragma unroll
    for (int r = 0; r < 8; r++)
        dst[(size_t)(b * NG + h * 8 + r) * DIMC + c] = __float2half(acc[r]);
}

// ------------------------- fp16 NT GEMM template ----------------------------
// C[M,N] = A[M,K] * B[N,K]^T.  A,B fp16 packed as uint32 k-pairs.
// Block tile 64m x 128n, K-stage 32 (16 words), double-buffered, 8 warps 2x4.
__global__ __launch_bounds__(256)
void gemm_f16_nt(const uint32_t* __restrict__ Aw, const uint32_t* __restrict__ Bw,
                 float* __restrict__ Cf,
                 int a_row_w, int b_row_w, int c_row,
                 int a_mat_w, int b_mat_w, int c_mat, int KT) {
    int b = blockIdx.z;
    const uint32_t* A = Aw + (size_t)b * a_mat_w;
    const uint32_t* B = Bw + (size_t)b * b_mat_w;
    float* C = Cf + (size_t)b * c_mat;
    int m0 = blockIdx.y * 64, n0 = blockIdx.x * 128;
    __shared__ uint32_t As[2][64 * 20];
    __shared__ uint32_t Bs[2][128 * 20];
    int tid = threadIdx.x, lane = tid & 31, warp = tid >> 5;
    int wm = warp >> 2, wn = warp & 3;
    int g = lane >> 2, t = lane & 3;
    float acc[2][4][4];
#pragma unroll
    for (int mi = 0; mi < 2; mi++)
#pragma unroll
        for (int ni = 0; ni < 4; ni++)
#pragma unroll
            for (int q = 0; q < 4; q++) acc[mi][ni][q] = 0.f;

    // per-thread load coords (stage = 16 words per row)
    int am = tid & 63,  aw4 = (tid >> 6) * 4;        // 1 uint4 for A
    int bn = tid & 127, bw4 = (tid >> 7) * 4;        // 2 uint4 for B (bw4, bw4+8)
    const uint32_t* Ap = A + (size_t)(m0 + am) * a_row_w + aw4;
    const uint32_t* Bp = B + (size_t)(n0 + bn) * b_row_w + bw4;

    uint4 ra  = *(const uint4*)Ap;
    uint4 rb0 = *(const uint4*)Bp;
    uint4 rb1 = *(const uint4*)(Bp + 8);
    // store stage 0
    *(uint4*)&As[0][am * 20 + aw4]     = ra;
    *(uint4*)&Bs[0][bn * 20 + bw4]     = rb0;
    *(uint4*)&Bs[0][bn * 20 + bw4 + 8] = rb1;

    for (int kt = 0; kt < KT; kt++) {
        __syncthreads();
        int cur = kt & 1;
        bool more = (kt + 1 < KT);
        if (more) {
            int ko = (kt + 1) * 16;
            ra  = *(const uint4*)(Ap + ko);
            rb0 = *(const uint4*)(Bp + ko);
            rb1 = *(const uint4*)(Bp + ko + 8);
        }
#pragma unroll
        for (int kk = 0; kk < 2; kk++) {
            uint32_t af[2][4];
#pragma unroll
            for (int mi = 0; mi < 2; mi++) {
                int base = (wm * 32 + mi * 16 + g) * 20 + kk * 8;
                af[mi][0] = As[cur][base + t];
                af[mi][1] = As[cur][base + 160 + t];        // row +8
                af[mi][2] = As[cur][base + t + 4];
                af[mi][3] = As[cur][base + 160 + t + 4];
            }
#pragma unroll
            for (int ni = 0; ni < 4; ni++) {
                int bb = (wn * 32 + ni * 8 + g) * 20 + kk * 8;
                uint32_t bf[2] = { Bs[cur][bb + t], Bs[cur][bb + t + 4] };
                mma_f16(acc[0][ni], af[0], bf);
                mma_f16(acc[1][ni], af[1], bf);
            }
        }
        if (more) {
            int nxt = cur ^ 1;
            *(uint4*)&As[nxt][am * 20 + aw4]     = ra;
            *(uint4*)&Bs[nxt][bn * 20 + bw4]     = rb0;
            *(uint4*)&Bs[nxt][bn * 20 + bw4 + 8] = rb1;
        }
    }
#pragma unroll
    for (int mi = 0; mi < 2; mi++)
#pragma unroll
        for (int ni = 0; ni < 4; ni++) {
            int row = m0 + wm * 32 + mi * 16 + g;
            int col = n0 + wn * 32 + ni * 8 + 2 * t;
            float2 v0 = make_float2(acc[mi][ni][0], acc[mi][ni][1]);
            float2 v1 = make_float2(acc[mi][ni][2], acc[mi][ni][3]);
            *(float2*)&C[(size_t)row * c_row + col] = v0;
            *(float2*)&C[(size_t)(row + 8) * c_row + col] = v1;
        }
}

// ------------------------- masked softmax (fp32 in, fp16 out) ---------------
__global__ __launch_bounds__(256)
void softmax_kernel(const void* __restrict__ mask) {
    int b = blockIdx.y, gg = blockIdx.x;
    int r = gg & 7;
    const float* row = g_p + (size_t)(b * NG + gg) * NTOK;
    __half* prow = (__half*)g_ph + (size_t)(b * NG + gg) * NTOK;
    int tid = threadIdx.x, lane = tid & 31, warp = tid >> 5;
    int mode = g_maskmode;
    __shared__ float s1[8], s2[8];

    float vals[16];
    float mx = -1e30f;
#pragma unroll
    for (int j = 0; j < 16; j++) {
        int n = j * 256 + tid;
        float v = row[n];
        bool keep;
        if (n < RR) {
            keep = (n == r);
        } else {
            int mi = (b * RR + r) * MASKW + (n - RR);
            if (mode == 0)      keep = ((const int*)mask)[mi] != 0;
            else if (mode == 1) keep = ((const unsigned char*)mask)[mi] != 0;
            else                keep = ((const float*)mask)[mi] != 0.f;
        }
        v = keep ? v : -1e30f;
        vals[j] = v;
        mx = fmaxf(mx, v);
    }
#pragma unroll
    for (int o = 16; o > 0; o >>= 1) mx = fmaxf(mx, __shfl_xor_sync(0xffffffffu, mx, o));
    if (lane == 0) s1[warp] = mx;
    __syncthreads();
    mx = s1[0];
#pragma unroll
    for (int w = 1; w < 8; w++) mx = fmaxf(mx, s1[w]);

    float sum = 0.f;
#pragma unroll
    for (int j = 0; j < 16; j++) {
        float e = expf(vals[j] - mx);
        vals[j] = e;
        sum += e;
    }
#pragma unroll
    for (int o = 16; o > 0; o >>= 1) sum += __shfl_xor_sync(0xffffffffu, sum, o);
    if (lane == 0) s2[warp] = sum;
    __syncthreads();
    sum = 0.f;
#pragma unroll
    for (int w = 0; w < 8; w++) sum += s2[w];
    float inv = 1.f / sum;
#pragma unroll
    for (int j = 0; j < 16; j++)
        prow[j * 256 + tid] = __float2half(vals[j] * inv);
}

// ------------------------- xcls: per-head Wv projection of y ----------------
__global__ __launch_bounds__(256)
void xcls_kernel(const float* __restrict__ Wv) {
    int h = blockIdx.x, b = blockIdx.y;
    __shared__ float ys[8][64];
    __shared__ float wvs[64][65];
    int tid = threadIdx.x;
    int r = tid >> 5, lane = tid & 31;
    int d0 = lane * 2;
    float a0 = 0.f, a1 = 0.f;
    for (int c0 = 0; c0 < DIMC; c0 += 64) {
        __syncthreads();
        for (int idx = tid; idx < 512; idx += 256) {
            int rr = idx >> 6, cc = idx & 63;
            ys[rr][cc] = g_y[(size_t)(b * NG + h * 8 + rr) * DIMC + c0 + cc];
        }
        for (int idx = tid; idx < 4096; idx += 256) {
            int dd = idx >> 6, cc = idx & 63;
            wvs[dd][cc] = Wv[(size_t)(h * HD + dd) * DIMC + c0 + cc];
        }
        __syncthreads();
#pragma unroll
        for (int cc = 0; cc < 64; cc++) {
            float yv = ys[r][cc];
            a0 += yv * wvs[d0][cc];
            a1 += yv * wvs[d0 + 1][cc];
        }
    }
    g_xcls[(size_t)(b * 8 + r) * DIMC + h * HD + d0]     = a0;
    g_xcls[(size_t)(b * 8 + r) * DIMC + h * HD + d0 + 1] = a1;
}

// ---------------------------------------------------------------------------
extern "C" void kernel_launch(void* const* d_in, const int* in_sizes, int n_in,
                              void* d_out, int out_size) {
    const float* x    = (const float*)d_in[0];
    const void*  mask = d_in[1];
    const float* Wq   = (const float*)d_in[2];
    const float* Wk   = (const float*)d_in[3];
    const float* Wv   = (const float*)d_in[4];
    const float* Wp   = (const float*)d_in[5];
    const float* bp   = (const float*)d_in[6];
    float* out = (float*)d_out;

    float*    d_x8;   cudaGetSymbolAddress((void**)&d_x8,   g_x8);
    float*    d_part; cudaGetSymbolAddress((void**)&d_part, g_part);
    float*    d_xcls; cudaGetSymbolAddress((void**)&d_xcls, g_xcls);
    float*    d_p;    cudaGetSymbolAddress((void**)&d_p,    g_p);
    float*    d_y;    cudaGetSymbolAddress((void**)&d_y,    g_y);
    uint32_t* d_xh;   cudaGetSymbolAddress((void**)&d_xh,   g_xh);
    uint32_t* d_xt;   cudaGetSymbolAddress((void**)&d_xt,   g_xt);
    uint32_t* d_qkh;  cudaGetSymbolAddress((void**)&d_qkh,  g_qkh);
    uint32_t* d_ph;   cudaGetSymbolAddress((void**)&d_ph,   g_ph);

    detect_mask_kernel<<<1, 128>>>((const unsigned int*)mask);
    conv_kernel<<<dim3(24, 64, NB), 256>>>(x);
    gather_x8_kernel<<<64, 256>>>(x);

    // q = x8 @ Wq^T (split-K 6) * SCALE
    small_nt_kernel<<<dim3(24, 6), 256>>>(d_x8, Wq, d_part);
    reduce_q_kernel<<<384, 256>>>();

    // qk per head (fp16 out)
    qk_kernel<<<dim3(12, NH, NB), 128>>>(Wk);

    // logits: [192,4096] = qkh[192,1536] @ x_h[4096,1536]^T
    gemm_f16_nt<<<dim3(32, 3, NB), 256>>>(
        d_qkh, d_xh, d_p,
        DIMC / 2, DIMC / 2, NTOK,
        NG * (DIMC / 2), NTOK * (DIMC / 2), NG * NTOK, DIMC / 32);

    softmax_kernel<<<dim3(NG, NB), 256>>>(mask);

    // y: [192,1536] = p_h[192,4096] @ x_t[1536,4096]^T
    gemm_f16_nt<<<dim3(12, 3, NB), 256>>>(
        d_ph, d_xt, d_y,
        NTOK / 2, NTOK / 2, DIMC,
        NG * (NTOK / 2), DIMC * (NTOK / 2), NG * DIMC, NTOK / 32);

    // per-head Wv projection, then output projection + bias
    xcls_kernel<<<dim3(NH, NB), 256>>>(Wv);
    small_nt_kernel<<<dim3(24, 6), 256>>>(d_xcls, Wp, d_part);
    reduce_out_kernel<<<384, 256>>>(bp, out);
}